// round 15
// baseline (speedup 1.0000x reference)
#include <cuda_runtime.h>
#include <math.h>
#include <stdint.h>

// ---------------------------------------------------------------------------
// DiagonalMicroAttention: b=8, c=256, h=w=32, heads=8, d=32, n=1024
//   K1 qkv GEMM via tf32 mma, cp.async ring, f2tf at fragment load
//   K2 colsum(V) + diag_vec (fused)
//   K3 flash attention via tf32 mma, 32 q-rows/warp, cp.async pipelined K/V
//   K4 gate hidden via tf32 mma, cp.async pipelined, pooled-on-the-fly
//   K5 out-proj via tf32 mma, cp.async ring, f2tf at frag load, gate fused
// ---------------------------------------------------------------------------

#define B 8
#define HEADS 8
#define D 32
#define N 1024
#define C 256
#define SCALE 0.1767766952966369f   // 1/sqrt(32)
#define LOG2E 1.4426950408889634f
#define BHND (B * HEADS * N * D)

__device__ __forceinline__ uint32_t f2tf(float f) {
    uint32_t r; asm("cvt.rna.tf32.f32 %0, %1;" : "=r"(r) : "f"(f));
    return r;
}
__device__ __forceinline__ uint32_t u2tf(uint32_t u) {
    uint32_t r; asm("cvt.rna.tf32.f32 %0, %1;" : "=r"(r) : "r"(u));
    return r;
}
__device__ __forceinline__ float ex2f(float x) {
    float r; asm("ex2.approx.ftz.f32 %0, %1;" : "=f"(r) : "f"(x));
    return r;
}
__device__ __forceinline__ void mma_tf32(float& d0, float& d1, float& d2, float& d3,
                                         uint32_t a0, uint32_t a1, uint32_t a2, uint32_t a3,
                                         uint32_t b0, uint32_t b1) {
    asm("mma.sync.aligned.m16n8k8.row.col.f32.tf32.tf32.f32 "
        "{%0,%1,%2,%3}, {%4,%5,%6,%7}, {%8,%9}, {%0,%1,%2,%3};"
        : "+f"(d0), "+f"(d1), "+f"(d2), "+f"(d3)
        : "r"(a0), "r"(a1), "r"(a2), "r"(a3), "r"(b0), "r"(b1));
}
__device__ __forceinline__ void cp16(uint32_t smem_addr, const void* gptr) {
    asm volatile("cp.async.cg.shared.global [%0], [%1], 16;"
                 :: "r"(smem_addr), "l"(gptr));
}

// in-row permutations for MMA-fragment-friendly K/V storage
__device__ __forceinline__ int physK(int d) {
    return (d & 3) * 8 + (d >> 3) * 2 + ((d >> 2) & 1);
}
__device__ __forceinline__ int physV(int d) {
    return (d & 7) * 4 + (d >> 3);
}

__device__ float g_q[BHND];                // logical layout, x SCALE*LOG2E
__device__ float g_k[BHND];                // physK-permuted rows
__device__ float g_v[BHND];                // physV-permuted rows
__device__ float g_ao[B * C * N];          // attention output, [b][c][n]
__device__ float g_g1buf[B * 64 * N];      // gate hidden
__device__ float g_dvec[B * D];            // ln2*0.3/8 * diag sums
__device__ float g_csum[B * HEADS * D];    // colsum of V, physV order

// ---------------------------------------------------------------------------
// K1: qkv projection via tf32 MMA, cp.async ring at 16-col K granularity.
// Fragments rounded to tf32 (.rna) in registers after LDS.
// ---------------------------------------------------------------------------
#define QWPAD 20
#define QXPAD 136

__global__ __launch_bounds__(256) void qkv_kernel(const float* __restrict__ x,
                                                  const float* __restrict__ w) {
    const int b = blockIdx.z;
    const int o0 = blockIdx.y * 128;
    const int p0 = blockIdx.x * 128;
    const int tid = threadIdx.x;
    const int warp = tid >> 5;
    const int lane = tid & 31;
    const int gid = lane >> 2;
    const int tig = lane & 3;
    const int o_w = (warp >> 2) * 64;
    const int p_w = (warp & 3) * 32;

    __shared__ uint32_t Ws[2][128 * QWPAD];   // [o][c16] raw fp32
    __shared__ uint32_t Xs[2][16 * QXPAD];    // [c16][p] raw fp32

    const uint32_t wsb = (uint32_t)__cvta_generic_to_shared(Ws);
    const uint32_t xsb = (uint32_t)__cvta_generic_to_shared(Xs);

    float acc[4][4][4];
#pragma unroll
    for (int m = 0; m < 4; m++)
#pragma unroll
        for (int n = 0; n < 4; n++)
#pragma unroll
            for (int r = 0; r < 4; r++) acc[m][n][r] = 0.f;

    const int w_oo = tid >> 2, w_c4 = (tid & 3) * 4;
    const int w_oo2 = (tid + 256) >> 2, w_c42 = ((tid + 256) & 3) * 4;
    const int x_cc = tid >> 5, x_p4 = (tid & 31) * 4;
    const int x_cc2 = (tid + 256) >> 5, x_p42 = ((tid + 256) & 31) * 4;
    const float* xb = x + (size_t)(b * 256) * 1024 + p0;

#pragma unroll
    for (int h = 0; h < 2; h++) {
        const int kk = h * 16;
        cp16(wsb + (h * 128 * QWPAD + w_oo * QWPAD + w_c4) * 4,
             &w[(o0 + w_oo) * 256 + kk + w_c4]);
        cp16(wsb + (h * 128 * QWPAD + w_oo2 * QWPAD + w_c42) * 4,
             &w[(o0 + w_oo2) * 256 + kk + w_c42]);
        cp16(xsb + (h * 16 * QXPAD + x_cc * QXPAD + x_p4) * 4,
             &xb[(size_t)(kk + x_cc) * 1024 + x_p4]);
        cp16(xsb + (h * 16 * QXPAD + x_cc2 * QXPAD + x_p42) * 4,
             &xb[(size_t)(kk + x_cc2) * 1024 + x_p42]);
        asm volatile("cp.async.commit_group;");
    }

    for (int h = 0; h < 16; h++) {
        if (h < 15) asm volatile("cp.async.wait_group 1;");
        else        asm volatile("cp.async.wait_group 0;");
        __syncthreads();

        const int rg = h & 1;
        const uint32_t* wbuf = Ws[rg];
        const uint32_t* xbuf = Xs[rg];
#pragma unroll
        for (int kc = 0; kc < 2; kc++) {
            const int ck = kc * 8;
            uint32_t af[4][4];
#pragma unroll
            for (int m = 0; m < 4; m++) {
                const uint32_t* wr = &wbuf[(o_w + m * 16 + gid) * QWPAD + ck + tig];
                af[m][0] = u2tf(wr[0]);
                af[m][1] = u2tf(wr[8 * QWPAD]);
                af[m][2] = u2tf(wr[4]);
                af[m][3] = u2tf(wr[8 * QWPAD + 4]);
            }
#pragma unroll
            for (int n = 0; n < 4; n++) {
                const uint32_t* xr = &xbuf[(ck + tig) * QXPAD + p_w + n * 8 + gid];
                uint32_t b0 = u2tf(xr[0]);
                uint32_t b1 = u2tf(xr[4 * QXPAD]);
#pragma unroll
                for (int m = 0; m < 4; m++)
                    mma_tf32(acc[m][n][0], acc[m][n][1], acc[m][n][2], acc[m][n][3],
                             af[m][0], af[m][1], af[m][2], af[m][3], b0, b1);
            }
        }
        __syncthreads();

        if (h + 2 < 16) {
            const int hn = h + 2;
            const int kk = hn * 16;
            const int rg2 = hn & 1;
            cp16(wsb + (rg2 * 128 * QWPAD + w_oo * QWPAD + w_c4) * 4,
                 &w[(o0 + w_oo) * 256 + kk + w_c4]);
            cp16(wsb + (rg2 * 128 * QWPAD + w_oo2 * QWPAD + w_c42) * 4,
                 &w[(o0 + w_oo2) * 256 + kk + w_c42]);
            cp16(xsb + (rg2 * 16 * QXPAD + x_cc * QXPAD + x_p4) * 4,
                 &xb[(size_t)(kk + x_cc) * 1024 + x_p4]);
            cp16(xsb + (rg2 * 16 * QXPAD + x_cc2 * QXPAD + x_p42) * 4,
                 &xb[(size_t)(kk + x_cc2) * 1024 + x_p42]);
            asm volatile("cp.async.commit_group;");
        }
    }

    // epilogue: route to q/k/v with per-part layout + scaling
    const int part = (o0 + o_w) >> 8;
    float* dst = (part == 0) ? g_q : ((part == 1) ? g_k : g_v);
    const float mult = (part == 0) ? (SCALE * LOG2E) : 1.0f;
#pragma unroll
    for (int m = 0; m < 4; m++) {
        const int ob = o0 + o_w + m * 16;
        const int head = (ob >> 5) & 7;
        const int dl0 = (ob & 31) + gid;
        const int dl1 = dl0 + 8;
        int d0, d1;
        if (part == 0)      { d0 = dl0;        d1 = dl1; }
        else if (part == 1) { d0 = physK(dl0); d1 = physK(dl1); }
        else                { d0 = physV(dl0); d1 = physV(dl1); }
        float* hb = dst + ((size_t)(b * 8 + head) * 1024) * 32;
#pragma unroll
        for (int n = 0; n < 4; n++) {
            const int p = p0 + p_w + n * 8 + 2 * tig;
            float* pb = hb + (size_t)p * 32;
            pb[d0]      = __uint_as_float(f2tf(acc[m][n][0] * mult));
            pb[32 + d0] = __uint_as_float(f2tf(acc[m][n][1] * mult));
            pb[d1]      = __uint_as_float(f2tf(acc[m][n][2] * mult));
            pb[32 + d1] = __uint_as_float(f2tf(acc[m][n][3] * mult));
        }
    }
}

// ---------------------------------------------------------------------------
// K2: fused colsum(V) (blocks 0..63) + diag_vec (blocks 64..71).
// ---------------------------------------------------------------------------
__global__ __launch_bounds__(256) void reduce_kernel() {
    const int tid = threadIdx.x;
    __shared__ float red[256];
    if (blockIdx.x < 64) {
        const int bh = blockIdx.x;
        const int dd = tid & 31;
        const int sl = tid >> 5;
        const float* vb = g_v + (size_t)bh * 1024 * 32;
        float s = 0.f;
        for (int j = sl * 128; j < sl * 128 + 128; j++) s += vb[(size_t)j * 32 + dd];
        red[tid] = s;
        __syncthreads();
        if (tid < 32) {
            float t = 0.f;
#pragma unroll
            for (int r = 0; r < 8; r++) t += red[tid + r * 32];
            g_csum[bh * 32 + tid] = t;
        }
    } else {
        const int b = blockIdx.x - 64;
        const int i = tid & 31;
        const int h = tid >> 5;
        const int ik = physK(i);
        const size_t base = ((size_t)(b * 8 + h) * 1024) * 32;
        float s = 0.f;
#pragma unroll 4
        for (int ss = 0; ss < 32; ss++) {
            size_t off = base + (size_t)(ss * 33) * 32;
            s += g_q[off + i] * g_k[off + ik];
        }
        red[tid] = s;
        __syncthreads();
        if (tid < 32) {
            float t = 0.f;
#pragma unroll
            for (int r = 0; r < 8; r++) t += red[tid + r * 32];
            g_dvec[b * 32 + tid] = t * (0.3f * 0.6931471805599453f / 8.0f);
        }
    }
}

// ---------------------------------------------------------------------------
// K3: tf32 flash attention, 4 warps/CTA, 32 q-rows/warp, cp.async-pipelined
// K/V staging (2-slot ring of 64-key halves inside the same smem footprint).
// ---------------------------------------------------------------------------
#define KPAD 36
#define VPAD 40

__global__ __launch_bounds__(128, 4) void attn_kernel() {
    const int bh = blockIdx.y;
    const int b = bh >> 3;
    const int head = bh & 7;
    const int tid = threadIdx.x;
    const int warp = tid >> 5;
    const int lane = tid & 31;
    const int gid = lane >> 2;
    const int tig = lane & 3;
    const int q0 = blockIdx.x * 128 + warp * 32;

    __shared__ uint32_t Ks[128 * KPAD];   // 2 x 64-key slots
    __shared__ uint32_t Vs[128 * VPAD];

    const float* qb = g_q + (size_t)bh * (N * D);
    uint32_t qa[2][4][4];
#pragma unroll
    for (int tt = 0; tt < 2; tt++) {
        const int rb = q0 + tt * 16;
#pragma unroll
        for (int kc = 0; kc < 4; kc++) {
            qa[tt][kc][0] = __float_as_uint(qb[(rb + gid) * 32 + kc * 8 + tig]);
            qa[tt][kc][1] = __float_as_uint(qb[(rb + gid + 8) * 32 + kc * 8 + tig]);
            qa[tt][kc][2] = __float_as_uint(qb[(rb + gid) * 32 + kc * 8 + tig + 4]);
            qa[tt][kc][3] = __float_as_uint(qb[(rb + gid + 8) * 32 + kc * 8 + tig + 4]);
        }
    }

    float o[2][4][4];
#pragma unroll
    for (int tt = 0; tt < 2; tt++)
#pragma unroll
        for (int nt = 0; nt < 4; nt++)
#pragma unroll
            for (int r = 0; r < 4; r++) o[tt][nt][r] = 0.f;
    float lv[2][2];
    lv[0][0] = lv[0][1] = lv[1][0] = lv[1][1] = 0.f;

    const uint4* kgl = (const uint4*)(g_k + (size_t)bh * (N * D));
    const uint4* vgl = (const uint4*)(g_v + (size_t)bh * (N * D));
    const uint32_t ksb = (uint32_t)__cvta_generic_to_shared(Ks);
    const uint32_t vsb = (uint32_t)__cvta_generic_to_shared(Vs);
    const int src0 = (lane & 28) | (tig >> 1);
    const bool odd = (tig & 1);

    const int lkey0 = tid >> 3;
    const int lc16 = tid & 7;

#pragma unroll
    for (int h = 0; h < 2; h++) {
#pragma unroll
        for (int r = 0; r < 4; r++) {
            int key = lkey0 + r * 16;
            cp16(ksb + (((h & 1) * 64 + key) * KPAD + lc16 * 4) * 4,
                 kgl + (size_t)(h * 64 + key) * 8 + lc16);
            cp16(vsb + (((h & 1) * 64 + key) * VPAD + lc16 * 4) * 4,
                 vgl + (size_t)(h * 64 + key) * 8 + lc16);
        }
        asm volatile("cp.async.commit_group;");
    }

    for (int h = 0; h < 16; h++) {
        if (h < 15) asm volatile("cp.async.wait_group 1;");
        else        asm volatile("cp.async.wait_group 0;");
        __syncthreads();

        const int rbase = (h & 1) * 64;
#pragma unroll 2
        for (int kch = 0; kch < 8; kch++) {
            const int key0 = rbase + kch * 8;
            const uint32_t* krow = &Ks[(key0 + gid) * KPAD + tig * 8];
            uint4 kf0 = *(const uint4*)krow;
            uint4 kf1 = *(const uint4*)(krow + 4);
            uint4 vf0 = *(const uint4*)&Vs[(key0 + tig) * VPAD + gid * 4];
            uint4 vf1 = *(const uint4*)&Vs[(key0 + tig + 4) * VPAD + gid * 4];

#pragma unroll
            for (int tt = 0; tt < 2; tt++) {
                float s0 = 0.f, s1 = 0.f, s2 = 0.f, s3 = 0.f;
                mma_tf32(s0, s1, s2, s3, qa[tt][0][0], qa[tt][0][1], qa[tt][0][2], qa[tt][0][3], kf0.x, kf0.y);
                mma_tf32(s0, s1, s2, s3, qa[tt][1][0], qa[tt][1][1], qa[tt][1][2], qa[tt][1][3], kf0.z, kf0.w);
                mma_tf32(s0, s1, s2, s3, qa[tt][2][0], qa[tt][2][1], qa[tt][2][2], qa[tt][2][3], kf1.x, kf1.y);
                mma_tf32(s0, s1, s2, s3, qa[tt][3][0], qa[tt][3][1], qa[tt][3][2], qa[tt][3][3], kf1.z, kf1.w);
                float f0 = ex2f(s0), f1 = ex2f(s1), f2 = ex2f(s2), f3 = ex2f(s3);
                lv[tt][0] += f0 + f1;
                lv[tt][1] += f2 + f3;
                uint32_t p0 = __float_as_uint(f0);
                uint32_t p1 = __float_as_uint(f1);
                uint32_t p2 = __float_as_uint(f2);
                uint32_t p3 = __float_as_uint(f3);
                uint32_t e0, e1;
                e0 = __shfl_sync(0xffffffffu, p0, src0);
                e1 = __shfl_sync(0xffffffffu, p1, src0);
                uint32_t pa0 = odd ? e1 : e0;
                e0 = __shfl_sync(0xffffffffu, p0, src0 + 2);
                e1 = __shfl_sync(0xffffffffu, p1, src0 + 2);
                uint32_t pa2 = odd ? e1 : e0;
                e0 = __shfl_sync(0xffffffffu, p2, src0);
                e1 = __shfl_sync(0xffffffffu, p3, src0);
                uint32_t pa1 = odd ? e1 : e0;
                e0 = __shfl_sync(0xffffffffu, p2, src0 + 2);
                e1 = __shfl_sync(0xffffffffu, p3, src0 + 2);
                uint32_t pa3 = odd ? e1 : e0;
                mma_tf32(o[tt][0][0], o[tt][0][1], o[tt][0][2], o[tt][0][3], pa0, pa1, pa2, pa3, vf0.x, vf1.x);
                mma_tf32(o[tt][1][0], o[tt][1][1], o[tt][1][2], o[tt][1][3], pa0, pa1, pa2, pa3, vf0.y, vf1.y);
                mma_tf32(o[tt][2][0], o[tt][2][1], o[tt][2][2], o[tt][2][3], pa0, pa1, pa2, pa3, vf0.z, vf1.z);
                mma_tf32(o[tt][3][0], o[tt][3][1], o[tt][3][2], o[tt][3][3], pa0, pa1, pa2, pa3, vf0.w, vf1.w);
            }
        }
        __syncthreads();

        if (h + 2 < 16) {
            const int hn = h + 2;
#pragma unroll
            for (int r = 0; r < 4; r++) {
                int key = lkey0 + r * 16;
                cp16(ksb + (((hn & 1) * 64 + key) * KPAD + lc16 * 4) * 4,
                     kgl + (size_t)(hn * 64 + key) * 8 + lc16);
                cp16(vsb + (((hn & 1) * 64 + key) * VPAD + lc16 * 4) * 4,
                     vgl + (size_t)(hn * 64 + key) * 8 + lc16);
            }
            asm volatile("cp.async.commit_group;");
        }
    }

    const float* cs = g_csum + bh * 32;   // physV order
    float* ob = g_ao + ((size_t)b * 256 + head * 32) * 1024;
#pragma unroll
    for (int tt = 0; tt < 2; tt++) {
        float llo = lv[tt][0], lhi = lv[tt][1];
        llo += __shfl_xor_sync(0xffffffffu, llo, 1);
        llo += __shfl_xor_sync(0xffffffffu, llo, 2);
        lhi += __shfl_xor_sync(0xffffffffu, lhi, 1);
        lhi += __shfl_xor_sync(0xffffffffu, lhi, 2);
        const float invlo = 1.f / llo;
        const float invhi = 1.f / lhi;

        const int rlo = q0 + tt * 16 + gid;
        const int rhi = rlo + 8;
        const float dvlo = (rlo < 32) ? g_dvec[b * 32 + rlo] : 0.f;
        const float dvhi = (rhi < 32) ? g_dvec[b * 32 + rhi] : 0.f;
#pragma unroll
        for (int nt = 0; nt < 4; nt++) {
            int c0 = nt * 8 + 2 * tig;
            int c1 = c0 + 1;
            float cs0 = cs[8 * tig + nt];          // physV(c0)
            float cs1 = cs[8 * tig + 4 + nt];      // physV(c1)
            ob[(size_t)c0 * 1024 + rlo] = o[tt][nt][0] * invlo + dvlo * cs0;
            ob[(size_t)c1 * 1024 + rlo] = o[tt][nt][1] * invlo + dvlo * cs1;
            ob[(size_t)c0 * 1024 + rhi] = o[tt][nt][2] * invhi + dvhi * cs0;
            ob[(size_t)c1 * 1024 + rhi] = o[tt][nt][3] * invhi + dvhi * cs1;
        }
    }
}

// ---------------------------------------------------------------------------
// K4: gate hidden via tf32 MMA, cp.async 2-deep ring, raw-fp32 MMA operands
// (truncation acceptable on the gate path), pooled |l-r| at frag load time.
// ---------------------------------------------------------------------------
#define G1WPAD 36
#define XRPAD 68

__global__ __launch_bounds__(256) void gate1_kernel(const float* __restrict__ x,
                                                    const float* __restrict__ w_g1,
                                                    const float* __restrict__ b_g1) {
    const int b = blockIdx.y;
    const int p0 = blockIdx.x * 64;
    const int tid = threadIdx.x;
    const int warp = tid >> 5;
    const int lane = tid & 31;
    const int gid = lane >> 2;
    const int tig = lane & 3;
    const int mw = warp & 3;      // 16-u tile
    const int nw = warp >> 2;     // 32-p half

    __shared__ uint32_t Ws[2][64 * G1WPAD];   // W ring, raw fp32 bits, [u][c]
    __shared__ float    Xr[2][32 * XRPAD];    // raw x ring, [c][64 floats]

    const uint32_t wsb = (uint32_t)__cvta_generic_to_shared(Ws);
    const uint32_t xrb = (uint32_t)__cvta_generic_to_shared(Xr);

    float acc[4][4];
#pragma unroll
    for (int n = 0; n < 4; n++)
#pragma unroll
        for (int r = 0; r < 4; r++) acc[n][r] = 0.f;

    int oA[4], oB[4];
#pragma unroll
    for (int n = 0; n < 4; n++) {
        int pp = nw * 32 + n * 8 + gid;
        int wj = (pp & 31) >> 1;
        oA[n] = (pp >> 5) * 32 + wj;
        oB[n] = (pp >> 5) * 32 + 31 - wj;
    }

    const float* xbase = x + (size_t)(b * 256) * 1024 + p0;
    const int w_uu = tid >> 3, w_c4 = (tid & 7) * 4;
    const int w_uu2 = (tid + 256) >> 3, w_c42 = ((tid + 256) & 7) * 4;
    const int x_cc = tid >> 4, x_f4 = (tid & 15) * 4;
    const int x_cc2 = (tid + 256) >> 4, x_f42 = ((tid + 256) & 15) * 4;

#pragma unroll
    for (int h = 0; h < 2; h++) {
        const int kk = h * 32;
        cp16(wsb + (h * 64 * G1WPAD + w_uu * G1WPAD + w_c4) * 4,
             &w_g1[w_uu * 256 + kk + w_c4]);
        cp16(wsb + (h * 64 * G1WPAD + w_uu2 * G1WPAD + w_c42) * 4,
             &w_g1[w_uu2 * 256 + kk + w_c42]);
        cp16(xrb + (h * 32 * XRPAD + x_cc * XRPAD + x_f4) * 4,
             &xbase[(size_t)(kk + x_cc) * 1024 + x_f4]);
        cp16(xrb + (h * 32 * XRPAD + x_cc2 * XRPAD + x_f42) * 4,
             &xbase[(size_t)(kk + x_cc2) * 1024 + x_f42]);
        asm volatile("cp.async.commit_group;");
    }

    for (int h = 0; h < 8; h++) {
        if (h < 7) asm volatile("cp.async.wait_group 1;");
        else       asm volatile("cp.async.wait_group 0;");
        __syncthreads();

        const int rg = h & 1;
        const uint32_t* wbuf = Ws[rg];
        const float* xbuf = Xr[rg];
#pragma unroll
        for (int kc = 0; kc < 4; kc++) {
            const int ck = kc * 8;
            const uint32_t* wr = &wbuf[(mw * 16 + gid) * G1WPAD + ck + tig];
            uint32_t a0 = wr[0];
            uint32_t a1 = wr[8 * G1WPAD];
            uint32_t a2 = wr[4];
            uint32_t a3 = wr[8 * G1WPAD + 4];
            const float* xr0 = &xbuf[(ck + tig) * XRPAD];
            const float* xr1 = &xbuf[(ck + tig + 4) * XRPAD];
#pragma unroll
            for (int n = 0; n < 4; n++) {
                uint32_t b0 = __float_as_uint(fabsf(xr0[oA[n]] - xr0[oB[n]]));
                uint32_t b1 = __float_as_uint(fabsf(xr1[oA[n]] - xr1[oB[n]]));
                mma_tf32(acc[n][0], acc[n][1], acc[n][2], acc[n][3],
                         a0, a1, a2, a3, b0, b1);
            }
        }
        __syncthreads();

        if (h + 2 < 8) {
            const int hn = h + 2;
            const int kk = hn * 32;
            const int rg2 = hn & 1;
            cp16(wsb + (rg2 * 64 * G1WPAD + w_uu * G1WPAD + w_c4) * 4,
                 &w_g1[w_uu * 256 + kk + w_c4]);
            cp16(wsb + (rg2 * 64 * G1WPAD + w_uu2 * G1WPAD + w_c42) * 4,
                 &w_g1[w_uu2 * 256 + kk + w_c42]);
            cp16(xrb + (rg2 * 32 * XRPAD + x_cc * XRPAD + x_f4) * 4,
                 &xbase[(size_t)(kk + x_cc) * 1024 + x_f4]);
            cp16(xrb + (rg2 * 32 * XRPAD + x_cc2 * XRPAD + x_f42) * 4,
                 &xbase[(size_t)(kk + x_cc2) * 1024 + x_f42]);
            asm volatile("cp.async.commit_group;");
        }
    }

    const int u0 = mw * 16 + gid;
    const int u1 = u0 + 8;
    const float bias0 = b_g1[u0];
    const float bias1 = b_g1[u1];
    float* g0 = g_g1buf + ((size_t)(b * 64) + u0) * 1024;
    float* g1 = g_g1buf + ((size_t)(b * 64) + u1) * 1024;
#pragma unroll
    for (int n = 0; n < 4; n++) {
        const int p = p0 + nw * 32 + n * 8 + 2 * tig;
        float v0 = acc[n][0] + bias0, v1 = acc[n][1] + bias0;
        float v2 = acc[n][2] + bias1, v3 = acc[n][3] + bias1;
        v0 = 0.5f * v0 * (1.f + erff(v0 * 0.70710678118654752f));
        v1 = 0.5f * v1 * (1.f + erff(v1 * 0.70710678118654752f));
        v2 = 0.5f * v2 * (1.f + erff(v2 * 0.70710678118654752f));
        v3 = 0.5f * v3 * (1.f + erff(v3 * 0.70710678118654752f));
        *(float2*)&g0[p] = make_float2(v0, v1);
        *(float2*)&g1[p] = make_float2(v2, v3);
    }
}

// ---------------------------------------------------------------------------
// K5: out-proj via tf32 MMA, cp.async ring; fragments tf32-rounded in regs;
// gate2 computed in-CTA, (1+g) applied at B-fragment load time.
// ---------------------------------------------------------------------------
__global__ __launch_bounds__(256) void outproj_kernel(const float* __restrict__ w_out,
                                                      const float* __restrict__ b_out,
                                                      const float* __restrict__ w_g2,
                                                      const float* __restrict__ b_g2,
                                                      float* __restrict__ out) {
    const int b = blockIdx.z;
    const int o0 = blockIdx.y * 128;
    const int p0 = blockIdx.x * 128;
    const int tid = threadIdx.x;
    const int warp = tid >> 5;
    const int lane = tid & 31;
    const int gid = lane >> 2;
    const int tig = lane & 3;
    const int o_w = (warp >> 2) * 64;
    const int p_w = (warp & 3) * 32;

    __shared__ uint32_t Ws[2][128 * QWPAD];
    __shared__ uint32_t Xs[2][16 * QXPAD];
    __shared__ float Gs[128];

    const uint32_t wsb = (uint32_t)__cvta_generic_to_shared(Ws);
    const uint32_t xsb = (uint32_t)__cvta_generic_to_shared(Xs);

    const int w_oo = tid >> 2, w_c4 = (tid & 3) * 4;
    const int w_oo2 = (tid + 256) >> 2, w_c42 = ((tid + 256) & 3) * 4;
    const int x_cc = tid >> 5, x_p4 = (tid & 31) * 4;
    const int x_cc2 = (tid + 256) >> 5, x_p42 = ((tid + 256) & 31) * 4;
    const float* ab = g_ao + (size_t)(b * 256) * 1024 + p0;

#pragma unroll
    for (int h = 0; h < 2; h++) {
        const int kk = h * 16;
        cp16(wsb + (h * 128 * QWPAD + w_oo * QWPAD + w_c4) * 4,
             &w_out[(o0 + w_oo) * 256 + kk + w_c4]);
        cp16(wsb + (h * 128 * QWPAD + w_oo2 * QWPAD + w_c42) * 4,
             &w_out[(o0 + w_oo2) * 256 + kk + w_c42]);
        cp16(xsb + (h * 16 * QXPAD + x_cc * QXPAD + x_p4) * 4,
             &ab[(size_t)(kk + x_cc) * 1024 + x_p4]);
        cp16(xsb + (h * 16 * QXPAD + x_cc2 * QXPAD + x_p42) * 4,
             &ab[(size_t)(kk + x_cc2) * 1024 + x_p42]);
        asm volatile("cp.async.commit_group;");
    }

    if (tid < 128) {
        float a = b_g2[0];
        const float* g1 = g_g1buf + (size_t)(b * 64) * 1024 + p0 + tid;
#pragma unroll 8
        for (int u = 0; u < 64; u++) a += g1[(size_t)u * 1024] * w_g2[u];
        Gs[tid] = 1.f + 1.f / (1.f + ex2f(-a * LOG2E));
    }
    __syncthreads();

    float gA[4];
#pragma unroll
    for (int n = 0; n < 4; n++) gA[n] = Gs[p_w + n * 8 + gid];

    float acc[4][4][4];
#pragma unroll
    for (int m = 0; m < 4; m++)
#pragma unroll
        for (int n = 0; n < 4; n++)
#pragma unroll
            for (int r = 0; r < 4; r++) acc[m][n][r] = 0.f;

    for (int h = 0; h < 16; h++) {
        if (h < 15) asm volatile("cp.async.wait_group 1;");
        else        asm volatile("cp.async.wait_group 0;");
        __syncthreads();

        const int rg = h & 1;
        const uint32_t* wbuf = Ws[rg];
        const uint32_t* xbuf = Xs[rg];
#pragma unroll
        for (int kc = 0; kc < 2; kc++) {
            const int ck = kc * 8;
            uint32_t af[4][4];
#pragma unroll
            for (int m = 0; m < 4; m++) {
                const uint32_t* wr = &wbuf[(o_w + m * 16 + gid) * QWPAD + ck + tig];
                af[m][0] = u2tf(wr[0]);
                af[m][1] = u2tf(wr[8 * QWPAD]);
                af[m][2] = u2tf(wr[4]);
                af[m][3] = u2tf(wr[8 * QWPAD + 4]);
            }
#pragma unroll
            for (int n = 0; n < 4; n++) {
                const uint32_t* xr = &xbuf[(ck + tig) * QXPAD + p_w + n * 8 + gid];
                uint32_t b0 = f2tf(__uint_as_float(xr[0]) * gA[n]);
                uint32_t b1 = f2tf(__uint_as_float(xr[4 * QXPAD]) * gA[n]);
#pragma unroll
                for (int m = 0; m < 4; m++)
                    mma_tf32(acc[m][n][0], acc[m][n][1], acc[m][n][2], acc[m][n][3],
                             af[m][0], af[m][1], af[m][2], af[m][3], b0, b1);
            }
        }
        __syncthreads();

        if (h + 2 < 16) {
            const int hn = h + 2;
            const int kk = hn * 16;
            const int rg2 = hn & 1;
            cp16(wsb + (rg2 * 128 * QWPAD + w_oo * QWPAD + w_c4) * 4,
                 &w_out[(o0 + w_oo) * 256 + kk + w_c4]);
            cp16(wsb + (rg2 * 128 * QWPAD + w_oo2 * QWPAD + w_c42) * 4,
                 &w_out[(o0 + w_oo2) * 256 + kk + w_c42]);
            cp16(xsb + (rg2 * 16 * QXPAD + x_cc * QXPAD + x_p4) * 4,
                 &ab[(size_t)(kk + x_cc) * 1024 + x_p4]);
            cp16(xsb + (rg2 * 16 * QXPAD + x_cc2 * QXPAD + x_p42) * 4,
                 &ab[(size_t)(kk + x_cc2) * 1024 + x_p42]);
            asm volatile("cp.async.commit_group;");
        }
    }

#pragma unroll
    for (int m = 0; m < 4; m++) {
        const int og0 = o0 + o_w + m * 16 + gid;
        const float bs0 = b_out[og0];
        const float bs1 = b_out[og0 + 8];
        float* r0 = out + ((size_t)(b * 256) + og0) * 1024;
        float* r1 = out + ((size_t)(b * 256) + og0 + 8) * 1024;
#pragma unroll
        for (int n = 0; n < 4; n++) {
            const int p = p0 + p_w + n * 8 + 2 * tig;
            *(float2*)&r0[p] = make_float2(acc[m][n][0] + bs0, acc[m][n][1] + bs0);
            *(float2*)&r1[p] = make_float2(acc[m][n][2] + bs1, acc[m][n][3] + bs1);
        }
    }
}

// ---------------------------------------------------------------------------
extern "C" void kernel_launch(void* const* d_in, const int* in_sizes, int n_in,
                              void* d_out, int out_size) {
    const float* x     = (const float*)d_in[0];
    const float* w_qkv = (const float*)d_in[1];
    const float* w_out = (const float*)d_in[2];
    const float* b_out = (const float*)d_in[3];
    const float* w_g1  = (const float*)d_in[4];
    const float* b_g1  = (const float*)d_in[5];
    const float* w_g2  = (const float*)d_in[6];
    const float* b_g2  = (const float*)d_in[7];
    float* out = (float*)d_out;

    qkv_kernel<<<dim3(8, 6, 8), 256>>>(x, w_qkv);
    reduce_kernel<<<72, 256>>>();
    attn_kernel<<<dim3(8, 64), 128>>>();
    gate1_kernel<<<dim3(16, 8), 256>>>(x, w_g1, b_g1);
    outproj_kernel<<<dim3(8, 2, 8), 256>>>(w_out, b_out, w_g2, b_g2, out);
}

// round 16
// speedup vs baseline: 1.1024x; 1.1024x over previous
#include <cuda_runtime.h>
#include <math.h>
#include <stdint.h>

// ---------------------------------------------------------------------------
// DiagonalMicroAttention: b=8, c=256, h=w=32, heads=8, d=32, n=1024
//   K1 qkv GEMM via tf32 mma, cp.async ring, f2tf at fragment load
//   K2 colsum(V) + diag_vec (fused)
//   K3 flash attention via tf32 mma, shfl-free P pass-through (key perm),
//      cp.async pipelined K/V
//   K4 gate hidden via tf32 mma, cp.async pipelined, pooled-on-the-fly
//   K5 out-proj via tf32 mma, cp.async ring, f2tf at frag load, gate fused
// ---------------------------------------------------------------------------

#define B 8
#define HEADS 8
#define D 32
#define N 1024
#define C 256
#define SCALE 0.1767766952966369f   // 1/sqrt(32)
#define LOG2E 1.4426950408889634f
#define BHND (B * HEADS * N * D)

__device__ __forceinline__ uint32_t f2tf(float f) {
    uint32_t r; asm("cvt.rna.tf32.f32 %0, %1;" : "=r"(r) : "f"(f));
    return r;
}
__device__ __forceinline__ uint32_t u2tf(uint32_t u) {
    uint32_t r; asm("cvt.rna.tf32.f32 %0, %1;" : "=r"(r) : "r"(u));
    return r;
}
__device__ __forceinline__ float ex2f(float x) {
    float r; asm("ex2.approx.ftz.f32 %0, %1;" : "=f"(r) : "f"(x));
    return r;
}
__device__ __forceinline__ void mma_tf32(float& d0, float& d1, float& d2, float& d3,
                                         uint32_t a0, uint32_t a1, uint32_t a2, uint32_t a3,
                                         uint32_t b0, uint32_t b1) {
    asm("mma.sync.aligned.m16n8k8.row.col.f32.tf32.tf32.f32 "
        "{%0,%1,%2,%3}, {%4,%5,%6,%7}, {%8,%9}, {%0,%1,%2,%3};"
        : "+f"(d0), "+f"(d1), "+f"(d2), "+f"(d3)
        : "r"(a0), "r"(a1), "r"(a2), "r"(a3), "r"(b0), "r"(b1));
}
__device__ __forceinline__ void cp16(uint32_t smem_addr, const void* gptr) {
    asm volatile("cp.async.cg.shared.global [%0], [%1], 16;"
                 :: "r"(smem_addr), "l"(gptr));
}

// in-row permutations for MMA-fragment-friendly K/V storage
__device__ __forceinline__ int physK(int d) {
    return (d & 3) * 8 + (d >> 3) * 2 + ((d >> 2) & 1);
}
__device__ __forceinline__ int physV(int d) {
    return (d & 7) * 4 + (d >> 3);
}

__device__ float g_q[BHND];                // logical layout, x SCALE*LOG2E
__device__ float g_k[BHND];                // physK-permuted rows
__device__ float g_v[BHND];                // physV-permuted rows
__device__ float g_ao[B * C * N];          // attention output, [b][c][n]
__device__ float g_g1buf[B * 64 * N];      // gate hidden
__device__ float g_dvec[B * D];            // ln2*0.3/8 * diag sums
__device__ float g_csum[B * HEADS * D];    // colsum of V, physV order

// ---------------------------------------------------------------------------
// K1: qkv projection via tf32 MMA, cp.async ring at 16-col K granularity.
// Fragments rounded to tf32 (.rna) in registers after LDS.
// ---------------------------------------------------------------------------
#define QWPAD 20
#define QXPAD 136

__global__ __launch_bounds__(256) void qkv_kernel(const float* __restrict__ x,
                                                  const float* __restrict__ w) {
    const int b = blockIdx.z;
    const int o0 = blockIdx.y * 128;
    const int p0 = blockIdx.x * 128;
    const int tid = threadIdx.x;
    const int warp = tid >> 5;
    const int lane = tid & 31;
    const int gid = lane >> 2;
    const int tig = lane & 3;
    const int o_w = (warp >> 2) * 64;
    const int p_w = (warp & 3) * 32;

    __shared__ uint32_t Ws[2][128 * QWPAD];   // [o][c16] raw fp32
    __shared__ uint32_t Xs[2][16 * QXPAD];    // [c16][p] raw fp32

    const uint32_t wsb = (uint32_t)__cvta_generic_to_shared(Ws);
    const uint32_t xsb = (uint32_t)__cvta_generic_to_shared(Xs);

    float acc[4][4][4];
#pragma unroll
    for (int m = 0; m < 4; m++)
#pragma unroll
        for (int n = 0; n < 4; n++)
#pragma unroll
            for (int r = 0; r < 4; r++) acc[m][n][r] = 0.f;

    const int w_oo = tid >> 2, w_c4 = (tid & 3) * 4;
    const int w_oo2 = (tid + 256) >> 2, w_c42 = ((tid + 256) & 3) * 4;
    const int x_cc = tid >> 5, x_p4 = (tid & 31) * 4;
    const int x_cc2 = (tid + 256) >> 5, x_p42 = ((tid + 256) & 31) * 4;
    const float* xb = x + (size_t)(b * 256) * 1024 + p0;

#pragma unroll
    for (int h = 0; h < 2; h++) {
        const int kk = h * 16;
        cp16(wsb + (h * 128 * QWPAD + w_oo * QWPAD + w_c4) * 4,
             &w[(o0 + w_oo) * 256 + kk + w_c4]);
        cp16(wsb + (h * 128 * QWPAD + w_oo2 * QWPAD + w_c42) * 4,
             &w[(o0 + w_oo2) * 256 + kk + w_c42]);
        cp16(xsb + (h * 16 * QXPAD + x_cc * QXPAD + x_p4) * 4,
             &xb[(size_t)(kk + x_cc) * 1024 + x_p4]);
        cp16(xsb + (h * 16 * QXPAD + x_cc2 * QXPAD + x_p42) * 4,
             &xb[(size_t)(kk + x_cc2) * 1024 + x_p42]);
        asm volatile("cp.async.commit_group;");
    }

    for (int h = 0; h < 16; h++) {
        if (h < 15) asm volatile("cp.async.wait_group 1;");
        else        asm volatile("cp.async.wait_group 0;");
        __syncthreads();

        const int rg = h & 1;
        const uint32_t* wbuf = Ws[rg];
        const uint32_t* xbuf = Xs[rg];
#pragma unroll
        for (int kc = 0; kc < 2; kc++) {
            const int ck = kc * 8;
            uint32_t af[4][4];
#pragma unroll
            for (int m = 0; m < 4; m++) {
                const uint32_t* wr = &wbuf[(o_w + m * 16 + gid) * QWPAD + ck + tig];
                af[m][0] = u2tf(wr[0]);
                af[m][1] = u2tf(wr[8 * QWPAD]);
                af[m][2] = u2tf(wr[4]);
                af[m][3] = u2tf(wr[8 * QWPAD + 4]);
            }
#pragma unroll
            for (int n = 0; n < 4; n++) {
                const uint32_t* xr = &xbuf[(ck + tig) * QXPAD + p_w + n * 8 + gid];
                uint32_t b0 = u2tf(xr[0]);
                uint32_t b1 = u2tf(xr[4 * QXPAD]);
#pragma unroll
                for (int m = 0; m < 4; m++)
                    mma_tf32(acc[m][n][0], acc[m][n][1], acc[m][n][2], acc[m][n][3],
                             af[m][0], af[m][1], af[m][2], af[m][3], b0, b1);
            }
        }
        __syncthreads();

        if (h + 2 < 16) {
            const int hn = h + 2;
            const int kk = hn * 16;
            const int rg2 = hn & 1;
            cp16(wsb + (rg2 * 128 * QWPAD + w_oo * QWPAD + w_c4) * 4,
                 &w[(o0 + w_oo) * 256 + kk + w_c4]);
            cp16(wsb + (rg2 * 128 * QWPAD + w_oo2 * QWPAD + w_c42) * 4,
                 &w[(o0 + w_oo2) * 256 + kk + w_c42]);
            cp16(xsb + (rg2 * 16 * QXPAD + x_cc * QXPAD + x_p4) * 4,
                 &xb[(size_t)(kk + x_cc) * 1024 + x_p4]);
            cp16(xsb + (rg2 * 16 * QXPAD + x_cc2 * QXPAD + x_p42) * 4,
                 &xb[(size_t)(kk + x_cc2) * 1024 + x_p42]);
            asm volatile("cp.async.commit_group;");
        }
    }

    // epilogue: route to q/k/v with per-part layout + scaling
    const int part = (o0 + o_w) >> 8;
    float* dst = (part == 0) ? g_q : ((part == 1) ? g_k : g_v);
    const float mult = (part == 0) ? (SCALE * LOG2E) : 1.0f;
#pragma unroll
    for (int m = 0; m < 4; m++) {
        const int ob = o0 + o_w + m * 16;
        const int head = (ob >> 5) & 7;
        const int dl0 = (ob & 31) + gid;
        const int dl1 = dl0 + 8;
        int d0, d1;
        if (part == 0)      { d0 = dl0;        d1 = dl1; }
        else if (part == 1) { d0 = physK(dl0); d1 = physK(dl1); }
        else                { d0 = physV(dl0); d1 = physV(dl1); }
        float* hb = dst + ((size_t)(b * 8 + head) * 1024) * 32;
#pragma unroll
        for (int n = 0; n < 4; n++) {
            const int p = p0 + p_w + n * 8 + 2 * tig;
            float* pb = hb + (size_t)p * 32;
            pb[d0]      = __uint_as_float(f2tf(acc[m][n][0] * mult));
            pb[32 + d0] = __uint_as_float(f2tf(acc[m][n][1] * mult));
            pb[d1]      = __uint_as_float(f2tf(acc[m][n][2] * mult));
            pb[32 + d1] = __uint_as_float(f2tf(acc[m][n][3] * mult));
        }
    }
}

// ---------------------------------------------------------------------------
// K2: fused colsum(V) (blocks 0..63) + diag_vec (blocks 64..71).
// ---------------------------------------------------------------------------
__global__ __launch_bounds__(256) void reduce_kernel() {
    const int tid = threadIdx.x;
    __shared__ float red[256];
    if (blockIdx.x < 64) {
        const int bh = blockIdx.x;
        const int dd = tid & 31;
        const int sl = tid >> 5;
        const float* vb = g_v + (size_t)bh * 1024 * 32;
        float s = 0.f;
        for (int j = sl * 128; j < sl * 128 + 128; j++) s += vb[(size_t)j * 32 + dd];
        red[tid] = s;
        __syncthreads();
        if (tid < 32) {
            float t = 0.f;
#pragma unroll
            for (int r = 0; r < 8; r++) t += red[tid + r * 32];
            g_csum[bh * 32 + tid] = t;
        }
    } else {
        const int b = blockIdx.x - 64;
        const int i = tid & 31;
        const int h = tid >> 5;
        const int ik = physK(i);
        const size_t base = ((size_t)(b * 8 + h) * 1024) * 32;
        float s = 0.f;
#pragma unroll 4
        for (int ss = 0; ss < 32; ss++) {
            size_t off = base + (size_t)(ss * 33) * 32;
            s += g_q[off + i] * g_k[off + ik];
        }
        red[tid] = s;
        __syncthreads();
        if (tid < 32) {
            float t = 0.f;
#pragma unroll
            for (int r = 0; r < 8; r++) t += red[tid + r * 32];
            g_dvec[b * 32 + tid] = t * (0.3f * 0.6931471805599453f / 8.0f);
        }
    }
}

// ---------------------------------------------------------------------------
// K3: tf32 flash attention, 4 warps/CTA, 32 q-rows/warp, cp.async-pipelined.
// Shfl-free softmax: P C-fragment is reused directly as the PV A-fragment
// {s0,s2,s1,s3} by loading V's B-fragment rows with key perm τ = {2t, 2t+1}.
// ---------------------------------------------------------------------------
#define KPAD 36
#define VPAD 36

__global__ __launch_bounds__(128, 4) void attn_kernel() {
    const int bh = blockIdx.y;
    const int b = bh >> 3;
    const int head = bh & 7;
    const int tid = threadIdx.x;
    const int warp = tid >> 5;
    const int lane = tid & 31;
    const int gid = lane >> 2;
    const int tig = lane & 3;
    const int q0 = blockIdx.x * 128 + warp * 32;

    __shared__ uint32_t Ks[128 * KPAD];   // 2 x 64-key slots
    __shared__ uint32_t Vs[128 * VPAD];

    const float* qb = g_q + (size_t)bh * (N * D);
    uint32_t qa[2][4][4];
#pragma unroll
    for (int tt = 0; tt < 2; tt++) {
        const int rb = q0 + tt * 16;
#pragma unroll
        for (int kc = 0; kc < 4; kc++) {
            qa[tt][kc][0] = __float_as_uint(qb[(rb + gid) * 32 + kc * 8 + tig]);
            qa[tt][kc][1] = __float_as_uint(qb[(rb + gid + 8) * 32 + kc * 8 + tig]);
            qa[tt][kc][2] = __float_as_uint(qb[(rb + gid) * 32 + kc * 8 + tig + 4]);
            qa[tt][kc][3] = __float_as_uint(qb[(rb + gid + 8) * 32 + kc * 8 + tig + 4]);
        }
    }

    float o[2][4][4];
#pragma unroll
    for (int tt = 0; tt < 2; tt++)
#pragma unroll
        for (int nt = 0; nt < 4; nt++)
#pragma unroll
            for (int r = 0; r < 4; r++) o[tt][nt][r] = 0.f;
    float lv[2][2];
    lv[0][0] = lv[0][1] = lv[1][0] = lv[1][1] = 0.f;

    const uint4* kgl = (const uint4*)(g_k + (size_t)bh * (N * D));
    const uint4* vgl = (const uint4*)(g_v + (size_t)bh * (N * D));
    const uint32_t ksb = (uint32_t)__cvta_generic_to_shared(Ks);
    const uint32_t vsb = (uint32_t)__cvta_generic_to_shared(Vs);

    const int lkey0 = tid >> 3;
    const int lc16 = tid & 7;

#pragma unroll
    for (int h = 0; h < 2; h++) {
#pragma unroll
        for (int r = 0; r < 4; r++) {
            int key = lkey0 + r * 16;
            cp16(ksb + (((h & 1) * 64 + key) * KPAD + lc16 * 4) * 4,
                 kgl + (size_t)(h * 64 + key) * 8 + lc16);
            cp16(vsb + (((h & 1) * 64 + key) * VPAD + lc16 * 4) * 4,
                 vgl + (size_t)(h * 64 + key) * 8 + lc16);
        }
        asm volatile("cp.async.commit_group;");
    }

    for (int h = 0; h < 16; h++) {
        if (h < 15) asm volatile("cp.async.wait_group 1;");
        else        asm volatile("cp.async.wait_group 0;");
        __syncthreads();

        const int rbase = (h & 1) * 64;
#pragma unroll 2
        for (int kch = 0; kch < 8; kch++) {
            const int key0 = rbase + kch * 8;
            const uint32_t* krow = &Ks[(key0 + gid) * KPAD + tig * 8];
            uint4 kf0 = *(const uint4*)krow;
            uint4 kf1 = *(const uint4*)(krow + 4);
            // V B-fragment rows with key perm τ: k=tig -> key 2tig,
            // k=tig+4 -> key 2tig+1 (so P's C-frag is a valid A-frag).
            uint4 vf0 = *(const uint4*)&Vs[(key0 + 2 * tig) * VPAD + gid * 4];
            uint4 vf1 = *(const uint4*)&Vs[(key0 + 2 * tig + 1) * VPAD + gid * 4];

#pragma unroll
            for (int tt = 0; tt < 2; tt++) {
                float s0 = 0.f, s1 = 0.f, s2 = 0.f, s3 = 0.f;
                mma_tf32(s0, s1, s2, s3, qa[tt][0][0], qa[tt][0][1], qa[tt][0][2], qa[tt][0][3], kf0.x, kf0.y);
                mma_tf32(s0, s1, s2, s3, qa[tt][1][0], qa[tt][1][1], qa[tt][1][2], qa[tt][1][3], kf0.z, kf0.w);
                mma_tf32(s0, s1, s2, s3, qa[tt][2][0], qa[tt][2][1], qa[tt][2][2], qa[tt][2][3], kf1.x, kf1.y);
                mma_tf32(s0, s1, s2, s3, qa[tt][3][0], qa[tt][3][1], qa[tt][3][2], qa[tt][3][3], kf1.z, kf1.w);
                float f0 = ex2f(s0), f1 = ex2f(s1), f2 = ex2f(s2), f3 = ex2f(s3);
                lv[tt][0] += f0 + f1;
                lv[tt][1] += f2 + f3;
                uint32_t p0 = __float_as_uint(f0);
                uint32_t p1 = __float_as_uint(f1);
                uint32_t p2 = __float_as_uint(f2);
                uint32_t p3 = __float_as_uint(f3);
                // A-frag = {s0, s2, s1, s3} under τ — no shuffles needed.
                mma_tf32(o[tt][0][0], o[tt][0][1], o[tt][0][2], o[tt][0][3], p0, p2, p1, p3, vf0.x, vf1.x);
                mma_tf32(o[tt][1][0], o[tt][1][1], o[tt][1][2], o[tt][1][3], p0, p2, p1, p3, vf0.y, vf1.y);
                mma_tf32(o[tt][2][0], o[tt][2][1], o[tt][2][2], o[tt][2][3], p0, p2, p1, p3, vf0.z, vf1.z);
                mma_tf32(o[tt][3][0], o[tt][3][1], o[tt][3][2], o[tt][3][3], p0, p2, p1, p3, vf0.w, vf1.w);
            }
        }
        __syncthreads();

        if (h + 2 < 16) {
            const int hn = h + 2;
#pragma unroll
            for (int r = 0; r < 4; r++) {
                int key = lkey0 + r * 16;
                cp16(ksb + (((hn & 1) * 64 + key) * KPAD + lc16 * 4) * 4,
                     kgl + (size_t)(hn * 64 + key) * 8 + lc16);
                cp16(vsb + (((hn & 1) * 64 + key) * VPAD + lc16 * 4) * 4,
                     vgl + (size_t)(hn * 64 + key) * 8 + lc16);
            }
            asm volatile("cp.async.commit_group;");
        }
    }

    const float* cs = g_csum + bh * 32;   // physV order
    float* ob = g_ao + ((size_t)b * 256 + head * 32) * 1024;
#pragma unroll
    for (int tt = 0; tt < 2; tt++) {
        float llo = lv[tt][0], lhi = lv[tt][1];
        llo += __shfl_xor_sync(0xffffffffu, llo, 1);
        llo += __shfl_xor_sync(0xffffffffu, llo, 2);
        lhi += __shfl_xor_sync(0xffffffffu, lhi, 1);
        lhi += __shfl_xor_sync(0xffffffffu, lhi, 2);
        const float invlo = 1.f / llo;
        const float invhi = 1.f / lhi;

        const int rlo = q0 + tt * 16 + gid;
        const int rhi = rlo + 8;
        const float dvlo = (rlo < 32) ? g_dvec[b * 32 + rlo] : 0.f;
        const float dvhi = (rhi < 32) ? g_dvec[b * 32 + rhi] : 0.f;
#pragma unroll
        for (int nt = 0; nt < 4; nt++) {
            int c0 = nt * 8 + 2 * tig;
            int c1 = c0 + 1;
            float cs0 = cs[8 * tig + nt];          // physV(c0)
            float cs1 = cs[8 * tig + 4 + nt];      // physV(c1)
            ob[(size_t)c0 * 1024 + rlo] = o[tt][nt][0] * invlo + dvlo * cs0;
            ob[(size_t)c1 * 1024 + rlo] = o[tt][nt][1] * invlo + dvlo * cs1;
            ob[(size_t)c0 * 1024 + rhi] = o[tt][nt][2] * invhi + dvhi * cs0;
            ob[(size_t)c1 * 1024 + rhi] = o[tt][nt][3] * invhi + dvhi * cs1;
        }
    }
}

// ---------------------------------------------------------------------------
// K4: gate hidden via tf32 MMA, cp.async 2-deep ring, raw-fp32 MMA operands
// (truncation acceptable on the gate path), pooled |l-r| at frag load time.
// ---------------------------------------------------------------------------
#define G1WPAD 36
#define XRPAD 68

__global__ __launch_bounds__(256) void gate1_kernel(const float* __restrict__ x,
                                                    const float* __restrict__ w_g1,
                                                    const float* __restrict__ b_g1) {
    const int b = blockIdx.y;
    const int p0 = blockIdx.x * 64;
    const int tid = threadIdx.x;
    const int warp = tid >> 5;
    const int lane = tid & 31;
    const int gid = lane >> 2;
    const int tig = lane & 3;
    const int mw = warp & 3;      // 16-u tile
    const int nw = warp >> 2;     // 32-p half

    __shared__ uint32_t Ws[2][64 * G1WPAD];   // W ring, raw fp32 bits, [u][c]
    __shared__ float    Xr[2][32 * XRPAD];    // raw x ring, [c][64 floats]

    const uint32_t wsb = (uint32_t)__cvta_generic_to_shared(Ws);
    const uint32_t xrb = (uint32_t)__cvta_generic_to_shared(Xr);

    float acc[4][4];
#pragma unroll
    for (int n = 0; n < 4; n++)
#pragma unroll
        for (int r = 0; r < 4; r++) acc[n][r] = 0.f;

    int oA[4], oB[4];
#pragma unroll
    for (int n = 0; n < 4; n++) {
        int pp = nw * 32 + n * 8 + gid;
        int wj = (pp & 31) >> 1;
        oA[n] = (pp >> 5) * 32 + wj;
        oB[n] = (pp >> 5) * 32 + 31 - wj;
    }

    const float* xbase = x + (size_t)(b * 256) * 1024 + p0;
    const int w_uu = tid >> 3, w_c4 = (tid & 7) * 4;
    const int w_uu2 = (tid + 256) >> 3, w_c42 = ((tid + 256) & 7) * 4;
    const int x_cc = tid >> 4, x_f4 = (tid & 15) * 4;
    const int x_cc2 = (tid + 256) >> 4, x_f42 = ((tid + 256) & 15) * 4;

#pragma unroll
    for (int h = 0; h < 2; h++) {
        const int kk = h * 32;
        cp16(wsb + (h * 64 * G1WPAD + w_uu * G1WPAD + w_c4) * 4,
             &w_g1[w_uu * 256 + kk + w_c4]);
        cp16(wsb + (h * 64 * G1WPAD + w_uu2 * G1WPAD + w_c42) * 4,
             &w_g1[w_uu2 * 256 + kk + w_c42]);
        cp16(xrb + (h * 32 * XRPAD + x_cc * XRPAD + x_f4) * 4,
             &xbase[(size_t)(kk + x_cc) * 1024 + x_f4]);
        cp16(xrb + (h * 32 * XRPAD + x_cc2 * XRPAD + x_f42) * 4,
             &xbase[(size_t)(kk + x_cc2) * 1024 + x_f42]);
        asm volatile("cp.async.commit_group;");
    }

    for (int h = 0; h < 8; h++) {
        if (h < 7) asm volatile("cp.async.wait_group 1;");
        else       asm volatile("cp.async.wait_group 0;");
        __syncthreads();

        const int rg = h & 1;
        const uint32_t* wbuf = Ws[rg];
        const float* xbuf = Xr[rg];
#pragma unroll
        for (int kc = 0; kc < 4; kc++) {
            const int ck = kc * 8;
            const uint32_t* wr = &wbuf[(mw * 16 + gid) * G1WPAD + ck + tig];
            uint32_t a0 = wr[0];
            uint32_t a1 = wr[8 * G1WPAD];
            uint32_t a2 = wr[4];
            uint32_t a3 = wr[8 * G1WPAD + 4];
            const float* xr0 = &xbuf[(ck + tig) * XRPAD];
            const float* xr1 = &xbuf[(ck + tig + 4) * XRPAD];
#pragma unroll
            for (int n = 0; n < 4; n++) {
                uint32_t b0 = __float_as_uint(fabsf(xr0[oA[n]] - xr0[oB[n]]));
                uint32_t b1 = __float_as_uint(fabsf(xr1[oA[n]] - xr1[oB[n]]));
                mma_tf32(acc[n][0], acc[n][1], acc[n][2], acc[n][3],
                         a0, a1, a2, a3, b0, b1);
            }
        }
        __syncthreads();

        if (h + 2 < 8) {
            const int hn = h + 2;
            const int kk = hn * 32;
            const int rg2 = hn & 1;
            cp16(wsb + (rg2 * 64 * G1WPAD + w_uu * G1WPAD + w_c4) * 4,
                 &w_g1[w_uu * 256 + kk + w_c4]);
            cp16(wsb + (rg2 * 64 * G1WPAD + w_uu2 * G1WPAD + w_c42) * 4,
                 &w_g1[w_uu2 * 256 + kk + w_c42]);
            cp16(xrb + (rg2 * 32 * XRPAD + x_cc * XRPAD + x_f4) * 4,
                 &xbase[(size_t)(kk + x_cc) * 1024 + x_f4]);
            cp16(xrb + (rg2 * 32 * XRPAD + x_cc2 * XRPAD + x_f42) * 4,
                 &xbase[(size_t)(kk + x_cc2) * 1024 + x_f42]);
            asm volatile("cp.async.commit_group;");
        }
    }

    const int u0 = mw * 16 + gid;
    const int u1 = u0 + 8;
    const float bias0 = b_g1[u0];
    const float bias1 = b_g1[u1];
    float* g0 = g_g1buf + ((size_t)(b * 64) + u0) * 1024;
    float* g1 = g_g1buf + ((size_t)(b * 64) + u1) * 1024;
#pragma unroll
    for (int n = 0; n < 4; n++) {
        const int p = p0 + nw * 32 + n * 8 + 2 * tig;
        float v0 = acc[n][0] + bias0, v1 = acc[n][1] + bias0;
        float v2 = acc[n][2] + bias1, v3 = acc[n][3] + bias1;
        v0 = 0.5f * v0 * (1.f + erff(v0 * 0.70710678118654752f));
        v1 = 0.5f * v1 * (1.f + erff(v1 * 0.70710678118654752f));
        v2 = 0.5f * v2 * (1.f + erff(v2 * 0.70710678118654752f));
        v3 = 0.5f * v3 * (1.f + erff(v3 * 0.70710678118654752f));
        *(float2*)&g0[p] = make_float2(v0, v1);
        *(float2*)&g1[p] = make_float2(v2, v3);
    }
}

// ---------------------------------------------------------------------------
// K5: out-proj via tf32 MMA, cp.async ring; fragments tf32-rounded in regs;
// gate2 computed in-CTA, (1+g) applied at B-fragment load time.
// ---------------------------------------------------------------------------
__global__ __launch_bounds__(256) void outproj_kernel(const float* __restrict__ w_out,
                                                      const float* __restrict__ b_out,
                                                      const float* __restrict__ w_g2,
                                                      const float* __restrict__ b_g2,
                                                      float* __restrict__ out) {
    const int b = blockIdx.z;
    const int o0 = blockIdx.y * 128;
    const int p0 = blockIdx.x * 128;
    const int tid = threadIdx.x;
    const int warp = tid >> 5;
    const int lane = tid & 31;
    const int gid = lane >> 2;
    const int tig = lane & 3;
    const int o_w = (warp >> 2) * 64;
    const int p_w = (warp & 3) * 32;

    __shared__ uint32_t Ws[2][128 * QWPAD];
    __shared__ uint32_t Xs[2][16 * QXPAD];
    __shared__ float Gs[128];

    const uint32_t wsb = (uint32_t)__cvta_generic_to_shared(Ws);
    const uint32_t xsb = (uint32_t)__cvta_generic_to_shared(Xs);

    const int w_oo = tid >> 2, w_c4 = (tid & 3) * 4;
    const int w_oo2 = (tid + 256) >> 2, w_c42 = ((tid + 256) & 3) * 4;
    const int x_cc = tid >> 5, x_p4 = (tid & 31) * 4;
    const int x_cc2 = (tid + 256) >> 5, x_p42 = ((tid + 256) & 31) * 4;
    const float* ab = g_ao + (size_t)(b * 256) * 1024 + p0;

#pragma unroll
    for (int h = 0; h < 2; h++) {
        const int kk = h * 16;
        cp16(wsb + (h * 128 * QWPAD + w_oo * QWPAD + w_c4) * 4,
             &w_out[(o0 + w_oo) * 256 + kk + w_c4]);
        cp16(wsb + (h * 128 * QWPAD + w_oo2 * QWPAD + w_c42) * 4,
             &w_out[(o0 + w_oo2) * 256 + kk + w_c42]);
        cp16(xsb + (h * 16 * QXPAD + x_cc * QXPAD + x_p4) * 4,
             &ab[(size_t)(kk + x_cc) * 1024 + x_p4]);
        cp16(xsb + (h * 16 * QXPAD + x_cc2 * QXPAD + x_p42) * 4,
             &ab[(size_t)(kk + x_cc2) * 1024 + x_p42]);
        asm volatile("cp.async.commit_group;");
    }

    if (tid < 128) {
        float a = b_g2[0];
        const float* g1 = g_g1buf + (size_t)(b * 64) * 1024 + p0 + tid;
#pragma unroll 8
        for (int u = 0; u < 64; u++) a += g1[(size_t)u * 1024] * w_g2[u];
        Gs[tid] = 1.f + 1.f / (1.f + ex2f(-a * LOG2E));
    }
    __syncthreads();

    float gA[4];
#pragma unroll
    for (int n = 0; n < 4; n++) gA[n] = Gs[p_w + n * 8 + gid];

    float acc[4][4][4];
#pragma unroll
    for (int m = 0; m < 4; m++)
#pragma unroll
        for (int n = 0; n < 4; n++)
#pragma unroll
            for (int r = 0; r < 4; r++) acc[m][n][r] = 0.f;

    for (int h = 0; h < 16; h++) {
        if (h < 15) asm volatile("cp.async.wait_group 1;");
        else        asm volatile("cp.async.wait_group 0;");
        __syncthreads();

        const int rg = h & 1;
        const uint32_t* wbuf = Ws[rg];
        const uint32_t* xbuf = Xs[rg];
#pragma unroll
        for (int kc = 0; kc < 2; kc++) {
            const int ck = kc * 8;
            uint32_t af[4][4];
#pragma unroll
            for (int m = 0; m < 4; m++) {
                const uint32_t* wr = &wbuf[(o_w + m * 16 + gid) * QWPAD + ck + tig];
                af[m][0] = u2tf(wr[0]);
                af[m][1] = u2tf(wr[8 * QWPAD]);
                af[m][2] = u2tf(wr[4]);
                af[m][3] = u2tf(wr[8 * QWPAD + 4]);
            }
#pragma unroll
            for (int n = 0; n < 4; n++) {
                const uint32_t* xr = &xbuf[(ck + tig) * QXPAD + p_w + n * 8 + gid];
                uint32_t b0 = f2tf(__uint_as_float(xr[0]) * gA[n]);
                uint32_t b1 = f2tf(__uint_as_float(xr[4 * QXPAD]) * gA[n]);
#pragma unroll
                for (int m = 0; m < 4; m++)
                    mma_tf32(acc[m][n][0], acc[m][n][1], acc[m][n][2], acc[m][n][3],
                             af[m][0], af[m][1], af[m][2], af[m][3], b0, b1);
            }
        }
        __syncthreads();

        if (h + 2 < 16) {
            const int hn = h + 2;
            const int kk = hn * 16;
            const int rg2 = hn & 1;
            cp16(wsb + (rg2 * 128 * QWPAD + w_oo * QWPAD + w_c4) * 4,
                 &w_out[(o0 + w_oo) * 256 + kk + w_c4]);
            cp16(wsb + (rg2 * 128 * QWPAD + w_oo2 * QWPAD + w_c42) * 4,
                 &w_out[(o0 + w_oo2) * 256 + kk + w_c42]);
            cp16(xsb + (rg2 * 16 * QXPAD + x_cc * QXPAD + x_p4) * 4,
                 &ab[(size_t)(kk + x_cc) * 1024 + x_p4]);
            cp16(xsb + (rg2 * 16 * QXPAD + x_cc2 * QXPAD + x_p42) * 4,
                 &ab[(size_t)(kk + x_cc2) * 1024 + x_p42]);
            asm volatile("cp.async.commit_group;");
        }
    }

#pragma unroll
    for (int m = 0; m < 4; m++) {
        const int og0 = o0 + o_w + m * 16 + gid;
        const float bs0 = b_out[og0];
        const float bs1 = b_out[og0 + 8];
        float* r0 = out + ((size_t)(b * 256) + og0) * 1024;
        float* r1 = out + ((size_t)(b * 256) + og0 + 8) * 1024;
#pragma unroll
        for (int n = 0; n < 4; n++) {
            const int p = p0 + p_w + n * 8 + 2 * tig;
            *(float2*)&r0[p] = make_float2(acc[m][n][0] + bs0, acc[m][n][1] + bs0);
            *(float2*)&r1[p] = make_float2(acc[m][n][2] + bs1, acc[m][n][3] + bs1);
        }
    }
}

// ---------------------------------------------------------------------------
extern "C" void kernel_launch(void* const* d_in, const int* in_sizes, int n_in,
                              void* d_out, int out_size) {
    const float* x     = (const float*)d_in[0];
    const float* w_qkv = (const float*)d_in[1];
    const float* w_out = (const float*)d_in[2];
    const float* b_out = (const float*)d_in[3];
    const float* w_g1  = (const float*)d_in[4];
    const float* b_g1  = (const float*)d_in[5];
    const float* w_g2  = (const float*)d_in[6];
    const float* b_g2  = (const float*)d_in[7];
    float* out = (float*)d_out;

    qkv_kernel<<<dim3(8, 6, 8), 256>>>(x, w_qkv);
    reduce_kernel<<<72, 256>>>();
    attn_kernel<<<dim3(8, 64), 128>>>();
    gate1_kernel<<<dim3(16, 8), 256>>>(x, w_g1, b_g1);
    outproj_kernel<<<dim3(8, 2, 8), 256>>>(w_out, b_out, w_g2, b_g2, out);
}